// round 15
// baseline (speedup 1.0000x reference)
#include <cuda_runtime.h>
#include <cuda_bf16.h>
#include <cuda_fp16.h>
#include <cstdint>

// Problem constants
#define NMAX   100000
#define NPAD   100128
#define DD     128
#define LL     3
#define OCW    512
#define CHN    4
#define CHID   256
#define EMAX   2000000

// ---------------- static device scratch ----------------
__device__ float g_cat[(size_t)NPAD * OCW];             // fp32 concat (gather source)
__device__ __half g_catF16[(size_t)NPAD * OCW];         // fp16 concat (MLP1 input)
__device__ __nv_bfloat16 g_a0[(size_t)NPAD * 256];      // conv input [hi128|lo128]
__device__ __nv_bfloat16 g_t0[(size_t)NPAD * 256];
__device__ __nv_bfloat16 g_t1[(size_t)NPAD * 256];
__device__ __half g_H1[(size_t)NPAD * 1024];            // fp16 [N,1024]
__device__ __nv_bfloat16 g_convWex[(size_t)9 * 128 * 384];   // bf16x3 [hi|lo|hi]
__device__ __half g_W1p[(size_t)CHN * 256 * 512];            // fp16 plain [N,K]
__device__ __half g_W2p[(size_t)CHN * 256 * 256];            // fp16 plain [N,K]
// CSR
__device__ int g_cnt   [NPAD + 1];
__device__ int g_rowptr[NPAD + 1];
__device__ int g_wp    [NPAD + 1];
__device__ int g_bsum  [256];
__device__ int g_csr   [EMAX];

// ---------------- helpers ----------------
__device__ __forceinline__ uint32_t smem_u32(const void* p) {
    uint32_t r;
    asm("{ .reg .u64 t; cvta.to.shared.u64 t, %1; cvt.u32.u64 %0, t; }" : "=r"(r) : "l"(p));
    return r;
}
#define LDSM_X4(r0, r1, r2, r3, addr) \
    asm volatile("ldmatrix.sync.aligned.m8n8.x4.shared.b16 {%0,%1,%2,%3}, [%4];" \
        : "=r"(r0), "=r"(r1), "=r"(r2), "=r"(r3) : "r"(addr))

__device__ __forceinline__ void mma_bf16(float* c, const uint32_t* a, uint32_t b0, uint32_t b1) {
    asm volatile(
        "mma.sync.aligned.m16n8k16.row.col.f32.bf16.bf16.f32 "
        "{%0,%1,%2,%3}, {%4,%5,%6,%7}, {%8,%9}, {%0,%1,%2,%3};"
        : "+f"(c[0]), "+f"(c[1]), "+f"(c[2]), "+f"(c[3])
        : "r"(a[0]), "r"(a[1]), "r"(a[2]), "r"(a[3]), "r"(b0), "r"(b1));
}
__device__ __forceinline__ void mma_fp16(float* c, const uint32_t* a, uint32_t b0, uint32_t b1) {
    asm volatile(
        "mma.sync.aligned.m16n8k16.row.col.f32.f16.f16.f32 "
        "{%0,%1,%2,%3}, {%4,%5,%6,%7}, {%8,%9}, {%0,%1,%2,%3};"
        : "+f"(c[0]), "+f"(c[1]), "+f"(c[2]), "+f"(c[3])
        : "r"(a[0]), "r"(a[1]), "r"(a[2]), "r"(a[3]), "r"(b0), "r"(b1));
}
__device__ __forceinline__ void cp16(uint32_t dst, const void* src) {
    asm volatile("cp.async.cg.shared.global [%0], [%1], 16;" :: "r"(dst), "l"(src));
}
#define CP_COMMIT() asm volatile("cp.async.commit_group;" ::: "memory")

// ---------------- weight expansion: bf16x3 [hi|lo|hi] ----------------
__global__ void expand_w_kernel(const float* __restrict__ W, __nv_bfloat16* __restrict__ Bex,
                                int K, int N) {
    int mi = blockIdx.y;
    const float* Wm = W + (size_t)mi * K * N;
    __nv_bfloat16* Bm = Bex + (size_t)mi * N * 3 * K;
    int id = blockIdx.x * blockDim.x + threadIdx.x;
    if (id >= K * N) return;
    int k = id / N, n = id % N;
    float w = Wm[id];
    __nv_bfloat16 hi = __float2bfloat16(w);
    __nv_bfloat16 lo = __float2bfloat16(w - __bfloat162float(hi));
    Bm[(size_t)n * 3 * K + k]         = hi;
    Bm[(size_t)n * 3 * K + K + k]     = lo;
    Bm[(size_t)n * 3 * K + 2 * K + k] = hi;
}

// ---------------- weight expansion: plain fp16 [N,K] ----------------
__global__ void expand_w16p_kernel(const float* __restrict__ W, __half* __restrict__ Bp,
                                   int K, int N) {
    int mi = blockIdx.y;
    const float* Wm = W + (size_t)mi * K * N;
    __half* Bm = Bp + (size_t)mi * N * K;
    int id = blockIdx.x * blockDim.x + threadIdx.x;
    if (id >= K * N) return;
    int k = id / N, n = id % N;
    Bm[(size_t)n * K + k] = __float2half(Wm[id]);
}

__device__ __forceinline__ void store_hilo4(__nv_bfloat16* p, int loDelta, float4 v) {
    __nv_bfloat16 h0 = __float2bfloat16(v.x), h1 = __float2bfloat16(v.y);
    __nv_bfloat16 h2 = __float2bfloat16(v.z), h3 = __float2bfloat16(v.w);
    ((__nv_bfloat162*)p)[0] = __nv_bfloat162(h0, h1);
    ((__nv_bfloat162*)p)[1] = __nv_bfloat162(h2, h3);
    __nv_bfloat16 l0 = __float2bfloat16(v.x - __bfloat162float(h0));
    __nv_bfloat16 l1 = __float2bfloat16(v.y - __bfloat162float(h1));
    __nv_bfloat16 l2 = __float2bfloat16(v.z - __bfloat162float(h2));
    __nv_bfloat16 l3 = __float2bfloat16(v.w - __bfloat162float(h3));
    ((__nv_bfloat162*)(p + loDelta))[0] = __nv_bfloat162(l0, l1);
    ((__nv_bfloat162*)(p + loDelta))[1] = __nv_bfloat162(l2, l3);
}

__global__ void prep_x_kernel(const float* __restrict__ x, int n) {
    int i = blockIdx.x * blockDim.x + threadIdx.x;
    if (i >= n * 32) return;
    int row = i >> 5, c4 = i & 31;
    float4 v = ((const float4*)x)[i];
    ((float4*)g_cat)[(size_t)row * 128 + c4] = v;
    __half* p = g_catF16 + (size_t)row * OCW + c4 * 4;
    ((__half2*)p)[0] = __floats2half2_rn(v.x, v.y);
    ((__half2*)p)[1] = __floats2half2_rn(v.z, v.w);
}

// ---------------- CSR build ----------------
__global__ void hist_kernel(const int* __restrict__ edge, int E) {
    int e = blockIdx.x * blockDim.x + threadIdx.x;
    if (e < E) atomicAdd(&g_cnt[__ldg(edge + E + e)], 1);
}
__global__ void scan1_kernel(int n) {
    __shared__ int warpSums[8];
    int t = threadIdx.x;
    int base = blockIdx.x * 1024 + t * 4;
    int v[4];
#pragma unroll
    for (int j = 0; j < 4; j++) v[j] = (base + j < n) ? g_cnt[base + j] : 0;
    int tsum = v[0] + v[1] + v[2] + v[3];
    int lane = t & 31, w = t >> 5;
    int x = tsum;
#pragma unroll
    for (int o = 1; o < 32; o <<= 1) {
        int y = __shfl_up_sync(0xffffffffu, x, o);
        if (lane >= o) x += y;
    }
    int excl = x - tsum;
    if (lane == 31) warpSums[w] = x;
    __syncthreads();
    if (t == 0) {
        int run = 0;
#pragma unroll
        for (int i = 0; i < 8; i++) { int tm = warpSums[i]; warpSums[i] = run; run += tm; }
        g_bsum[blockIdx.x] = run;
    }
    __syncthreads();
    int off = warpSums[w] + excl;
#pragma unroll
    for (int j = 0; j < 4; j++) {
        if (base + j < n) g_rowptr[base + j] = off;
        off += v[j];
    }
}
__global__ void scan2_kernel(int nb) {
    if (threadIdx.x == 0) {
        int run = 0;
        for (int i = 0; i < nb; i++) { int t = g_bsum[i]; g_bsum[i] = run; run += t; }
    }
}
__global__ void scan3_kernel(int n, int E) {
    int i = blockIdx.x * blockDim.x + threadIdx.x;
    if (i < n) {
        int v = g_rowptr[i] + g_bsum[i >> 10];
        g_rowptr[i] = v;
        g_wp[i] = v;
    }
    if (i == 0) g_rowptr[n] = E;
}
__global__ void fill_kernel(const int* __restrict__ edge, int E) {
    int e = blockIdx.x * blockDim.x + threadIdx.x;
    if (e >= E) return;
    int s = __ldg(edge + e);
    int d = __ldg(edge + E + e);
    int pos = atomicAdd(&g_wp[d], 1);
    g_csr[pos] = s;
}

// ---------------- gather + prep fused (unroll-4, order-preserving) ----------------
__global__ void gather_kernel(int n, int colOff) {
    int w = (blockIdx.x * blockDim.x + threadIdx.x) >> 5;
    if (w >= n) return;
    int lane = threadIdx.x & 31;
    int beg = __ldg(&g_rowptr[w]);
    int end = __ldg(&g_rowptr[w + 1]);
    const float* base = g_cat + colOff + lane * 4;
    float4 s = *(const float4*)(base + (size_t)w * OCW);
    int i = beg;
    for (; i + 3 < end; i += 4) {
        int s0 = __ldg(&g_csr[i]);
        int s1 = __ldg(&g_csr[i + 1]);
        int s2 = __ldg(&g_csr[i + 2]);
        int s3 = __ldg(&g_csr[i + 3]);
        float4 v0 = *(const float4*)(base + (size_t)s0 * OCW);
        float4 v1 = *(const float4*)(base + (size_t)s1 * OCW);
        float4 v2 = *(const float4*)(base + (size_t)s2 * OCW);
        float4 v3 = *(const float4*)(base + (size_t)s3 * OCW);
        s.x += v0.x; s.y += v0.y; s.z += v0.z; s.w += v0.w;
        s.x += v1.x; s.y += v1.y; s.z += v1.z; s.w += v1.w;
        s.x += v2.x; s.y += v2.y; s.z += v2.z; s.w += v2.w;
        s.x += v3.x; s.y += v3.y; s.z += v3.z; s.w += v3.w;
    }
    for (; i < end; i++) {
        int s0 = __ldg(&g_csr[i]);
        float4 v0 = *(const float4*)(base + (size_t)s0 * OCW);
        s.x += v0.x; s.y += v0.y; s.z += v0.z; s.w += v0.w;
    }
    store_hilo4(g_a0 + (size_t)w * 256 + lane * 4, 128, s);
}

// ---------------- conv GEMM (bf16x3), 128x128 tile, cp.async 3-stage ----------------
// MODE 0: relu(acc+bias) -> bf16 hi/lo outH
// MODE 1: relu(acc+bias) -> fp32 outF + fp16 outG
#define STAGES      3
#define ROWB        144
#define A_BYTES     (128 * ROWB)
#define STAGE_BYTES (2 * A_BYTES)

template<int MODE>
__global__ void __launch_bounds__(256, 2)
mma_gemm(const __nv_bfloat16* __restrict__ A, int lda, int loOffA,
         int K, int Kex,
         const __nv_bfloat16* __restrict__ Bx,
         const float* __restrict__ bias,
         float* __restrict__ outF, int ldF,
         __nv_bfloat16* __restrict__ outH, int ldH, int loDeltaOut,
         __half* __restrict__ outG, int ldG, int M)
{
    extern __shared__ char smem[];
    uint32_t sb = smem_u32(smem);

    int tid = threadIdx.x;
    int lane = tid & 31;
    int wid = tid >> 5;
    int warpM = wid & 1;
    int warpN = wid >> 1;
    int m0 = blockIdx.y * 128;

    float acc[4][4][4];
#pragma unroll
    for (int i = 0; i < 4; i++)
#pragma unroll
        for (int j = 0; j < 4; j++)
#pragma unroll
            for (int r = 0; r < 4; r++) acc[i][j][r] = 0.f;

    const int C = Kex / 64;

    auto ISSUE = [&](int c) {
        uint32_t st = sb + (c % STAGES) * STAGE_BYTES;
        int e0 = c * 64;
#pragma unroll
        for (int i = 0; i < 4; i++) {
            int id = tid + i * 256;
            int row = id >> 3;
            int kg  = id & 7;
            int e = e0 + kg * 8;
            int src = e < K ? e : (e < 2 * K ? e - K : e - 2 * K + loOffA);
            cp16(st + row * ROWB + kg * 16, A + (size_t)(m0 + row) * lda + src);
            cp16(st + A_BYTES + row * ROWB + kg * 16, Bx + (size_t)row * Kex + e);
        }
        CP_COMMIT();
    };

    ISSUE(0);
    if (C > 1) ISSUE(1);

    for (int c = 0; c < C; c++) {
        if (c == C - 1) asm volatile("cp.async.wait_group 0;" ::: "memory");
        else            asm volatile("cp.async.wait_group 1;" ::: "memory");
        __syncthreads();
        if (c + STAGES - 1 < C) ISSUE(c + STAGES - 1);

        uint32_t aBase = sb + (c % STAGES) * STAGE_BYTES;
        uint32_t bBase = aBase + A_BYTES;

#pragma unroll
        for (int ks = 0; ks < 4; ks++) {
            uint32_t af[4][4], bf[2][4];
            int kcol = ks * 16 + (lane >> 4) * 8;
#pragma unroll
            for (int i = 0; i < 4; i++) {
                uint32_t addr = aBase + (uint32_t)((warpM * 64 + i * 16 + (lane & 15)) * ROWB + kcol * 2);
                LDSM_X4(af[i][0], af[i][1], af[i][2], af[i][3], addr);
            }
#pragma unroll
            for (int jj = 0; jj < 2; jj++) {
                uint32_t addr = bBase + (uint32_t)((warpN * 32 + jj * 16 + (lane & 15)) * ROWB + kcol * 2);
                LDSM_X4(bf[jj][0], bf[jj][1], bf[jj][2], bf[jj][3], addr);
            }
#pragma unroll
            for (int i = 0; i < 4; i++)
#pragma unroll
                for (int j = 0; j < 4; j++) {
                    int jj = j >> 1, sel = j & 1;
                    mma_bf16(acc[i][j], af[i], bf[jj][sel], bf[jj][sel + 2]);
                }
        }
        __syncthreads();
    }

    int groupID = lane >> 2;
    int tcol = (lane & 3) * 2;

    float bv0[4], bv1[4];
#pragma unroll
    for (int j = 0; j < 4; j++) {
        int colC = warpN * 32 + j * 8 + tcol;
        bv0[j] = __ldg(bias + colC);
        bv1[j] = __ldg(bias + colC + 1);
    }

#pragma unroll
    for (int i = 0; i < 4; i++) {
        int row0 = m0 + warpM * 64 + i * 16 + groupID;
        int row1 = row0 + 8;
#pragma unroll
        for (int j = 0; j < 4; j++) {
            int colC = warpN * 32 + j * 8 + tcol;
            float v00 = fmaxf(acc[i][j][0] + bv0[j], 0.f);
            float v01 = fmaxf(acc[i][j][1] + bv1[j], 0.f);
            float v10 = fmaxf(acc[i][j][2] + bv0[j], 0.f);
            float v11 = fmaxf(acc[i][j][3] + bv1[j], 0.f);

            if (MODE == 0) {
                __nv_bfloat16 h00 = __float2bfloat16(v00), h01 = __float2bfloat16(v01);
                __nv_bfloat16 h10 = __float2bfloat16(v10), h11 = __float2bfloat16(v11);
                __nv_bfloat16* p0h = outH + (size_t)row0 * ldH + colC;
                __nv_bfloat16* p1h = outH + (size_t)row1 * ldH + colC;
                *(__nv_bfloat162*)p0h = __nv_bfloat162(h00, h01);
                *(__nv_bfloat162*)p1h = __nv_bfloat162(h10, h11);
                __nv_bfloat16 l00 = __float2bfloat16(v00 - __bfloat162float(h00));
                __nv_bfloat16 l01 = __float2bfloat16(v01 - __bfloat162float(h01));
                __nv_bfloat16 l10 = __float2bfloat16(v10 - __bfloat162float(h10));
                __nv_bfloat16 l11 = __float2bfloat16(v11 - __bfloat162float(h11));
                *(__nv_bfloat162*)(p0h + loDeltaOut) = __nv_bfloat162(l00, l01);
                *(__nv_bfloat162*)(p1h + loDeltaOut) = __nv_bfloat162(l10, l11);
            } else {
                if (row0 < M) {
                    *(float2*)(outF + (size_t)row0 * ldF + colC) = make_float2(v00, v01);
                    *(__half2*)(outG + (size_t)row0 * ldG + colC) = __floats2half2_rn(v00, v01);
                }
                if (row1 < M) {
                    *(float2*)(outF + (size_t)row1 * ldF + colC) = make_float2(v10, v11);
                    *(__half2*)(outG + (size_t)row1 * ldG + colC) = __floats2half2_rn(v10, v11);
                }
            }
        }
    }
}

// ---------------- MLP GEMM: 128x256 tile, warp 64x64, fp16, 3-stage cp.async ----------------
// MODE 2: relu(acc+bias) -> fp16 outG (channel layout)
// MODE 3: fused final dot -> atomicAdd(outp)
#define MROWB    144
#define M_A_ST   (128 * MROWB)          // 18432
#define M_B_ST   (256 * MROWB)          // 36864
#define M_STAGE  (M_A_ST + M_B_ST)      // 55296
#define M_STAGES 3
#define MLP_SMEM (M_STAGES * M_STAGE)   // 165888

template<int MODE>
__global__ void __launch_bounds__(256, 1)
mlp_gemm(const __half* __restrict__ A, int lda, int aChanStride, int K,
         const __half* __restrict__ Bx, long bChanStride,
         const float* __restrict__ bias, int biasChanStride,
         __half* __restrict__ outG, int ldG, int outGChanStride,
         const float* __restrict__ W3, float* __restrict__ outp, int M)
{
    extern __shared__ char smem[];
    uint32_t sb = smem_u32(smem);

    int tid = threadIdx.x;
    int lane = tid & 31;
    int wid = tid >> 5;
    int warpM = wid & 1;      // 2 groups of 64 rows
    int warpN = wid >> 1;     // 4 groups of 64 cols

    int cblk = blockIdx.x;    // channel
    int m0 = blockIdx.y * 128;

    const __half* Ab = A + (size_t)cblk * aChanStride;
    const __half* Bb = Bx + (size_t)cblk * bChanStride;

    float acc[4][8][4];
#pragma unroll
    for (int i = 0; i < 4; i++)
#pragma unroll
        for (int j = 0; j < 8; j++)
#pragma unroll
            for (int r = 0; r < 4; r++) acc[i][j][r] = 0.f;

    const int C = K / 64;

    auto ISSUE = [&](int c) {
        uint32_t st = sb + (c % M_STAGES) * M_STAGE;
        int e0 = c * 64;
#pragma unroll
        for (int i = 0; i < 4; i++) {       // A: 128 rows
            int id = tid + i * 256;
            int row = id >> 3;
            int kg  = id & 7;
            cp16(st + row * MROWB + kg * 16,
                 Ab + (size_t)(m0 + row) * lda + e0 + kg * 8);
        }
#pragma unroll
        for (int i = 0; i < 8; i++) {       // B: 256 rows
            int id = tid + i * 256;
            int row = id >> 3;
            int kg  = id & 7;
            cp16(st + M_A_ST + row * MROWB + kg * 16,
                 Bb + (size_t)row * K + e0 + kg * 8);
        }
        CP_COMMIT();
    };

    ISSUE(0);
    if (C > 1) ISSUE(1);

    for (int c = 0; c < C; c++) {
        if (c == C - 1) asm volatile("cp.async.wait_group 0;" ::: "memory");
        else            asm volatile("cp.async.wait_group 1;" ::: "memory");
        __syncthreads();
        if (c + M_STAGES - 1 < C) ISSUE(c + M_STAGES - 1);

        uint32_t aBase = sb + (c % M_STAGES) * M_STAGE;
        uint32_t bBase = aBase + M_A_ST;

#pragma unroll
        for (int ks = 0; ks < 4; ks++) {
            uint32_t af[4][4], bf[4][4];
            int kcol = ks * 16 + (lane >> 4) * 8;
#pragma unroll
            for (int i = 0; i < 4; i++) {
                uint32_t addr = aBase + (uint32_t)((warpM * 64 + i * 16 + (lane & 15)) * MROWB + kcol * 2);
                LDSM_X4(af[i][0], af[i][1], af[i][2], af[i][3], addr);
            }
#pragma unroll
            for (int jj = 0; jj < 4; jj++) {
                uint32_t addr = bBase + (uint32_t)((warpN * 64 + jj * 16 + (lane & 15)) * MROWB + kcol * 2);
                LDSM_X4(bf[jj][0], bf[jj][1], bf[jj][2], bf[jj][3], addr);
            }
#pragma unroll
            for (int i = 0; i < 4; i++)
#pragma unroll
                for (int j = 0; j < 8; j++) {
                    int jj = j >> 1, sel = j & 1;
                    mma_fp16(acc[i][j], af[i], bf[jj][sel], bf[jj][sel + 2]);
                }
        }
        __syncthreads();
    }

    // ---------------- epilogue ----------------
    int groupID = lane >> 2;
    int tcol = (lane & 3) * 2;

    float bv0[8], bv1[8], wv0[8], wv1[8];
#pragma unroll
    for (int j = 0; j < 8; j++) {
        int colC = warpN * 64 + j * 8 + tcol;
        const float* bp = bias + (size_t)cblk * biasChanStride + colC;
        bv0[j] = __ldg(bp);
        bv1[j] = __ldg(bp + 1);
        if (MODE == 3) {
            wv0[j] = __ldg(W3 + (size_t)cblk * CHID + colC);
            wv1[j] = __ldg(W3 + (size_t)cblk * CHID + colC + 1);
        }
    }

#pragma unroll
    for (int i = 0; i < 4; i++) {
        int row0 = m0 + warpM * 64 + i * 16 + groupID;
        int row1 = row0 + 8;
        if (MODE == 3) {
            float p0 = 0.f, p1 = 0.f;
#pragma unroll
            for (int j = 0; j < 8; j++) {
                float v00 = fmaxf(acc[i][j][0] + bv0[j], 0.f);
                float v01 = fmaxf(acc[i][j][1] + bv1[j], 0.f);
                float v10 = fmaxf(acc[i][j][2] + bv0[j], 0.f);
                float v11 = fmaxf(acc[i][j][3] + bv1[j], 0.f);
                p0 += v00 * wv0[j] + v01 * wv1[j];
                p1 += v10 * wv0[j] + v11 * wv1[j];
            }
            p0 += __shfl_xor_sync(0xffffffffu, p0, 1);
            p0 += __shfl_xor_sync(0xffffffffu, p0, 2);
            p1 += __shfl_xor_sync(0xffffffffu, p1, 1);
            p1 += __shfl_xor_sync(0xffffffffu, p1, 2);
            if ((lane & 3) == 0) {
                if (row0 < M) atomicAdd(outp + (size_t)row0 * CHN + cblk, p0);
                if (row1 < M) atomicAdd(outp + (size_t)row1 * CHN + cblk, p1);
            }
        } else {
#pragma unroll
            for (int j = 0; j < 8; j++) {
                int colC = warpN * 64 + j * 8 + tcol;
                float v00 = fmaxf(acc[i][j][0] + bv0[j], 0.f);
                float v01 = fmaxf(acc[i][j][1] + bv1[j], 0.f);
                float v10 = fmaxf(acc[i][j][2] + bv0[j], 0.f);
                float v11 = fmaxf(acc[i][j][3] + bv1[j], 0.f);
                __half* p0g = outG + (size_t)row0 * ldG + cblk * outGChanStride + colC;
                __half* p1g = outG + (size_t)row1 * ldG + cblk * outGChanStride + colC;
                *(__half2*)p0g = __floats2half2_rn(v00, v01);
                *(__half2*)p1g = __floats2half2_rn(v10, v11);
            }
        }
    }
}

__global__ void out_bias_relu_kernel(float* __restrict__ out, const float* __restrict__ b3, int n) {
    int i = blockIdx.x * blockDim.x + threadIdx.x;
    if (i >= n * CHN) return;
    float v = out[i] + b3[i & (CHN - 1)];
    out[i] = v > 0.f ? v : 0.f;
}

// ---------------- launch ----------------
extern "C" void kernel_launch(void* const* d_in, const int* in_sizes, int n_in,
                              void* d_out, int out_size)
{
    const float* x     = (const float*)d_in[0];
    const int*   edge  = (const int*)  d_in[1];
    const float* convW = (const float*)d_in[2];
    const float* convB = (const float*)d_in[3];
    const float* cW1   = (const float*)d_in[4];
    const float* cB1   = (const float*)d_in[5];
    const float* cW2   = (const float*)d_in[6];
    const float* cB2   = (const float*)d_in[7];
    const float* cW3   = (const float*)d_in[8];
    const float* cB3   = (const float*)d_in[9];
    float* out = (float*)d_out;

    int n = in_sizes[0] / DD;
    int E = in_sizes[1] / 2;

    float *cat;
    __nv_bfloat16 *convWex, *a0, *t0, *t1;
    __half *W1p, *W2p, *catF16, *H1;
    int *cnt;
    cudaGetSymbolAddress((void**)&cat, g_cat);
    cudaGetSymbolAddress((void**)&catF16, g_catF16);
    cudaGetSymbolAddress((void**)&a0, g_a0);
    cudaGetSymbolAddress((void**)&t0, g_t0);
    cudaGetSymbolAddress((void**)&t1, g_t1);
    cudaGetSymbolAddress((void**)&H1, g_H1);
    cudaGetSymbolAddress((void**)&convWex, g_convWex);
    cudaGetSymbolAddress((void**)&W1p, g_W1p);
    cudaGetSymbolAddress((void**)&W2p, g_W2p);
    cudaGetSymbolAddress((void**)&cnt, g_cnt);

    const int DSMEM = STAGES * STAGE_BYTES;
    cudaFuncSetAttribute(mma_gemm<0>, cudaFuncAttributeMaxDynamicSharedMemorySize, DSMEM);
    cudaFuncSetAttribute(mma_gemm<1>, cudaFuncAttributeMaxDynamicSharedMemorySize, DSMEM);
    cudaFuncSetAttribute(mlp_gemm<2>, cudaFuncAttributeMaxDynamicSharedMemorySize, MLP_SMEM);
    cudaFuncSetAttribute(mlp_gemm<3>, cudaFuncAttributeMaxDynamicSharedMemorySize, MLP_SMEM);

    const int mBlocks = (n + 127) / 128;

    // weight expansion
    { dim3 g((128 * 128 + 255) / 256, 9); expand_w_kernel<<<g, 256>>>(convW, convWex, 128, 128); }
    { dim3 g((512 * 256 + 255) / 256, CHN); expand_w16p_kernel<<<g, 256>>>(cW1, W1p, 512, 256); }
    { dim3 g((256 * 256 + 255) / 256, CHN); expand_w16p_kernel<<<g, 256>>>(cW2, W2p, 256, 256); }

    prep_x_kernel<<<(n * 32 + 255) / 256, 256>>>(x, n);

    // CSR build (once)
    cudaMemsetAsync(cnt, 0, (size_t)(n + 1) * sizeof(int), 0);
    hist_kernel<<<(E + 255) / 256, 256>>>(edge, E);
    int nb = (n + 1023) / 1024;
    scan1_kernel<<<nb, 256>>>(n);
    scan2_kernel<<<1, 32>>>(nb);
    scan3_kernel<<<(n + 255) / 256, 256>>>(n, E);
    fill_kernel<<<(E + 255) / 256, 256>>>(edge, E);

    for (int l = 0; l < LL; l++) {
        {
            long th = (long)n * 32;
            gather_kernel<<<(int)((th + 255) / 256), 256>>>(n, l * DD);
        }

        const float* b0 = convB + (size_t)(l * 3 + 0) * DD;
        const float* b1 = convB + (size_t)(l * 3 + 1) * DD;
        const float* b2 = convB + (size_t)(l * 3 + 2) * DD;
        const __nv_bfloat16* B0 = convWex + (size_t)(l * 3 + 0) * 128 * 384;
        const __nv_bfloat16* B1 = convWex + (size_t)(l * 3 + 1) * 128 * 384;
        const __nv_bfloat16* B2 = convWex + (size_t)(l * 3 + 2) * 128 * 384;

        dim3 grid(1, mBlocks);
        mma_gemm<0><<<grid, 256, DSMEM>>>(a0, 256, 128, 128, 384, B0, b0,
                                          nullptr, 0, t0, 256, 128, nullptr, 0, n);
        mma_gemm<0><<<grid, 256, DSMEM>>>(t0, 256, 128, 128, 384, B1, b1,
                                          nullptr, 0, t1, 256, 128, nullptr, 0, n);
        mma_gemm<1><<<grid, 256, DSMEM>>>(t1, 256, 128, 128, 384, B2, b2,
                                          cat + (l + 1) * DD, OCW,
                                          nullptr, 0, 0,
                                          catF16 + (l + 1) * DD, OCW, n);
    }

    // channel MLP layer 1: fp16 128x256 tiles, K=512 -> H1 fp16 [N,1024]
    {
        dim3 grid(CHN, mBlocks);
        mlp_gemm<2><<<grid, 256, MLP_SMEM>>>(catF16, OCW, 0, 512,
                                             W1p, (long)256 * 512,
                                             cB1, CHID,
                                             H1, 1024, CHID,
                                             nullptr, nullptr, n);
    }

    // channel MLP layer 2 + fused final dot: K=256
    cudaMemsetAsync(out, 0, (size_t)n * CHN * sizeof(float), 0);
    {
        dim3 grid(CHN, mBlocks);
        mlp_gemm<3><<<grid, 256, MLP_SMEM>>>(H1, 1024, 256, 256,
                                             W2p, (long)256 * 256,
                                             cB2, CHID,
                                             nullptr, 0, 0,
                                             cW3, out, n);
    }

    out_bias_relu_kernel<<<(n * CHN + 255) / 256, 256>>>(out, cB3, n);
}

// round 16
// speedup vs baseline: 1.0324x; 1.0324x over previous
#include <cuda_runtime.h>
#include <cuda_bf16.h>
#include <cuda_fp16.h>
#include <cstdint>

// Problem constants
#define NMAX   100000
#define NPAD   100128
#define DD     128
#define LL     3
#define OCW    512
#define CHN    4
#define CHID   256
#define EMAX   2000000

// ---------------- static device scratch ----------------
__device__ float g_cat[(size_t)NPAD * OCW];             // fp32 concat (gather source)
__device__ __half g_catF16[(size_t)NPAD * OCW];         // fp16 concat (MLP1 input)
__device__ __nv_bfloat16 g_a0[(size_t)NPAD * 256];      // conv input [hi128|lo128]
__device__ __nv_bfloat16 g_t0[(size_t)NPAD * 256];
__device__ __nv_bfloat16 g_t1[(size_t)NPAD * 256];
__device__ __half g_H1[(size_t)NPAD * 1024];            // fp16 [N,1024]
__device__ __nv_bfloat16 g_convWex[(size_t)9 * 128 * 384];   // bf16x3 [hi|lo|hi]
__device__ __half g_W1p[(size_t)CHN * 256 * 512];            // fp16 plain [N,K]
__device__ __half g_W2p[(size_t)CHN * 256 * 256];            // fp16 plain [N,K]
// CSR
__device__ int g_cnt   [NPAD + 1];
__device__ int g_rowptr[NPAD + 1];
__device__ int g_wp    [NPAD + 1];
__device__ int g_bsum  [256];
__device__ int g_csr   [EMAX];

// ---------------- helpers ----------------
__device__ __forceinline__ uint32_t smem_u32(const void* p) {
    uint32_t r;
    asm("{ .reg .u64 t; cvta.to.shared.u64 t, %1; cvt.u32.u64 %0, t; }" : "=r"(r) : "l"(p));
    return r;
}
#define LDSM_X4(r0, r1, r2, r3, addr) \
    asm volatile("ldmatrix.sync.aligned.m8n8.x4.shared.b16 {%0,%1,%2,%3}, [%4];" \
        : "=r"(r0), "=r"(r1), "=r"(r2), "=r"(r3) : "r"(addr))

__device__ __forceinline__ void mma_bf16(float* c, const uint32_t* a, uint32_t b0, uint32_t b1) {
    asm volatile(
        "mma.sync.aligned.m16n8k16.row.col.f32.bf16.bf16.f32 "
        "{%0,%1,%2,%3}, {%4,%5,%6,%7}, {%8,%9}, {%0,%1,%2,%3};"
        : "+f"(c[0]), "+f"(c[1]), "+f"(c[2]), "+f"(c[3])
        : "r"(a[0]), "r"(a[1]), "r"(a[2]), "r"(a[3]), "r"(b0), "r"(b1));
}
__device__ __forceinline__ void mma_fp16(float* c, const uint32_t* a, uint32_t b0, uint32_t b1) {
    asm volatile(
        "mma.sync.aligned.m16n8k16.row.col.f32.f16.f16.f32 "
        "{%0,%1,%2,%3}, {%4,%5,%6,%7}, {%8,%9}, {%0,%1,%2,%3};"
        : "+f"(c[0]), "+f"(c[1]), "+f"(c[2]), "+f"(c[3])
        : "r"(a[0]), "r"(a[1]), "r"(a[2]), "r"(a[3]), "r"(b0), "r"(b1));
}
__device__ __forceinline__ void cp16(uint32_t dst, const void* src) {
    asm volatile("cp.async.cg.shared.global [%0], [%1], 16;" :: "r"(dst), "l"(src));
}
#define CP_COMMIT() asm volatile("cp.async.commit_group;" ::: "memory")

// ---------------- weight expansion: bf16x3 [hi|lo|hi] ----------------
__global__ void expand_w_kernel(const float* __restrict__ W, __nv_bfloat16* __restrict__ Bex,
                                int K, int N) {
    int mi = blockIdx.y;
    const float* Wm = W + (size_t)mi * K * N;
    __nv_bfloat16* Bm = Bex + (size_t)mi * N * 3 * K;
    int id = blockIdx.x * blockDim.x + threadIdx.x;
    if (id >= K * N) return;
    int k = id / N, n = id % N;
    float w = Wm[id];
    __nv_bfloat16 hi = __float2bfloat16(w);
    __nv_bfloat16 lo = __float2bfloat16(w - __bfloat162float(hi));
    Bm[(size_t)n * 3 * K + k]         = hi;
    Bm[(size_t)n * 3 * K + K + k]     = lo;
    Bm[(size_t)n * 3 * K + 2 * K + k] = hi;
}

// ---------------- weight expansion: plain fp16 [N,K] ----------------
__global__ void expand_w16p_kernel(const float* __restrict__ W, __half* __restrict__ Bp,
                                   int K, int N) {
    int mi = blockIdx.y;
    const float* Wm = W + (size_t)mi * K * N;
    __half* Bm = Bp + (size_t)mi * N * K;
    int id = blockIdx.x * blockDim.x + threadIdx.x;
    if (id >= K * N) return;
    int k = id / N, n = id % N;
    Bm[(size_t)n * K + k] = __float2half(Wm[id]);
}

__device__ __forceinline__ void store_hilo4(__nv_bfloat16* p, int loDelta, float4 v) {
    __nv_bfloat16 h0 = __float2bfloat16(v.x), h1 = __float2bfloat16(v.y);
    __nv_bfloat16 h2 = __float2bfloat16(v.z), h3 = __float2bfloat16(v.w);
    ((__nv_bfloat162*)p)[0] = __nv_bfloat162(h0, h1);
    ((__nv_bfloat162*)p)[1] = __nv_bfloat162(h2, h3);
    __nv_bfloat16 l0 = __float2bfloat16(v.x - __bfloat162float(h0));
    __nv_bfloat16 l1 = __float2bfloat16(v.y - __bfloat162float(h1));
    __nv_bfloat16 l2 = __float2bfloat16(v.z - __bfloat162float(h2));
    __nv_bfloat16 l3 = __float2bfloat16(v.w - __bfloat162float(h3));
    ((__nv_bfloat162*)(p + loDelta))[0] = __nv_bfloat162(l0, l1);
    ((__nv_bfloat162*)(p + loDelta))[1] = __nv_bfloat162(l2, l3);
}

__global__ void prep_x_kernel(const float* __restrict__ x, int n) {
    int i = blockIdx.x * blockDim.x + threadIdx.x;
    if (i >= n * 32) return;
    int row = i >> 5, c4 = i & 31;
    float4 v = ((const float4*)x)[i];
    ((float4*)g_cat)[(size_t)row * 128 + c4] = v;
    __half* p = g_catF16 + (size_t)row * OCW + c4 * 4;
    ((__half2*)p)[0] = __floats2half2_rn(v.x, v.y);
    ((__half2*)p)[1] = __floats2half2_rn(v.z, v.w);
}

// ---------------- CSR build ----------------
__global__ void hist_kernel(const int* __restrict__ edge, int E) {
    int e = blockIdx.x * blockDim.x + threadIdx.x;
    if (e < E) atomicAdd(&g_cnt[__ldg(edge + E + e)], 1);
}
__global__ void scan1_kernel(int n) {
    __shared__ int warpSums[8];
    int t = threadIdx.x;
    int base = blockIdx.x * 1024 + t * 4;
    int v[4];
#pragma unroll
    for (int j = 0; j < 4; j++) v[j] = (base + j < n) ? g_cnt[base + j] : 0;
    int tsum = v[0] + v[1] + v[2] + v[3];
    int lane = t & 31, w = t >> 5;
    int x = tsum;
#pragma unroll
    for (int o = 1; o < 32; o <<= 1) {
        int y = __shfl_up_sync(0xffffffffu, x, o);
        if (lane >= o) x += y;
    }
    int excl = x - tsum;
    if (lane == 31) warpSums[w] = x;
    __syncthreads();
    if (t == 0) {
        int run = 0;
#pragma unroll
        for (int i = 0; i < 8; i++) { int tm = warpSums[i]; warpSums[i] = run; run += tm; }
        g_bsum[blockIdx.x] = run;
    }
    __syncthreads();
    int off = warpSums[w] + excl;
#pragma unroll
    for (int j = 0; j < 4; j++) {
        if (base + j < n) g_rowptr[base + j] = off;
        off += v[j];
    }
}
__global__ void scan2_kernel(int nb) {
    if (threadIdx.x == 0) {
        int run = 0;
        for (int i = 0; i < nb; i++) { int t = g_bsum[i]; g_bsum[i] = run; run += t; }
    }
}
__global__ void scan3_kernel(int n, int E) {
    int i = blockIdx.x * blockDim.x + threadIdx.x;
    if (i < n) {
        int v = g_rowptr[i] + g_bsum[i >> 10];
        g_rowptr[i] = v;
        g_wp[i] = v;
    }
    if (i == 0) g_rowptr[n] = E;
}
__global__ void fill_kernel(const int* __restrict__ edge, int E) {
    int e = blockIdx.x * blockDim.x + threadIdx.x;
    if (e >= E) return;
    int s = __ldg(edge + e);
    int d = __ldg(edge + E + e);
    int pos = atomicAdd(&g_wp[d], 1);
    g_csr[pos] = s;
}

// ---------------- gather + prep fused (unroll-4, order-preserving) ----------------
__global__ void gather_kernel(int n, int colOff) {
    int w = (blockIdx.x * blockDim.x + threadIdx.x) >> 5;
    if (w >= n) return;
    int lane = threadIdx.x & 31;
    int beg = __ldg(&g_rowptr[w]);
    int end = __ldg(&g_rowptr[w + 1]);
    const float* base = g_cat + colOff + lane * 4;
    float4 s = *(const float4*)(base + (size_t)w * OCW);
    int i = beg;
    for (; i + 3 < end; i += 4) {
        int s0 = __ldg(&g_csr[i]);
        int s1 = __ldg(&g_csr[i + 1]);
        int s2 = __ldg(&g_csr[i + 2]);
        int s3 = __ldg(&g_csr[i + 3]);
        float4 v0 = *(const float4*)(base + (size_t)s0 * OCW);
        float4 v1 = *(const float4*)(base + (size_t)s1 * OCW);
        float4 v2 = *(const float4*)(base + (size_t)s2 * OCW);
        float4 v3 = *(const float4*)(base + (size_t)s3 * OCW);
        s.x += v0.x; s.y += v0.y; s.z += v0.z; s.w += v0.w;
        s.x += v1.x; s.y += v1.y; s.z += v1.z; s.w += v1.w;
        s.x += v2.x; s.y += v2.y; s.z += v2.z; s.w += v2.w;
        s.x += v3.x; s.y += v3.y; s.z += v3.z; s.w += v3.w;
    }
    for (; i < end; i++) {
        int s0 = __ldg(&g_csr[i]);
        float4 v0 = *(const float4*)(base + (size_t)s0 * OCW);
        s.x += v0.x; s.y += v0.y; s.z += v0.z; s.w += v0.w;
    }
    store_hilo4(g_a0 + (size_t)w * 256 + lane * 4, 128, s);
}

// ---------------- mma.sync GEMM, cp.async 3-stage pipeline ----------------
// DT=0: bf16x3 expanded (Kex=3K), A [hi|..|lo at loOffA], bf16 mma
// DT=2: plain fp16 (Kex=K), src=e
// MODE 0: relu(acc+bias) -> bf16 hi/lo outH
// MODE 1: relu(acc+bias) -> fp16 outG (+ fp32 outF only if non-null)
// MODE 2: relu(acc+bias) -> fp16 outG (channel layout)
// MODE 3: fused final dot -> atomicAdd(outp)
#define STAGES      3
#define ROWB        144
#define A_BYTES     (128 * ROWB)
#define STAGE_BYTES (2 * A_BYTES)

template<int MODE, int DT>
__global__ void __launch_bounds__(256, 2)
mma_gemm(const __nv_bfloat16* __restrict__ A, int lda, int aChanStride, int loOffA,
         int K, int Kex,
         const __nv_bfloat16* __restrict__ Bx, long bChanStride, int chanWidth,
         const float* __restrict__ bias, int biasChanStride,
         float* __restrict__ outF, int ldF,
         __nv_bfloat16* __restrict__ outH, int ldH, int outHChanStride, int loDeltaOut,
         __half* __restrict__ outG, int ldG, int outGChanStride,
         const float* __restrict__ W3, float* __restrict__ outp, int M)
{
    extern __shared__ char smem[];
    uint32_t sb = smem_u32(smem);

    int tid = threadIdx.x;
    int lane = tid & 31;
    int wid = tid >> 5;
    int warpM = wid & 1;
    int warpN = wid >> 1;

    int j0 = blockIdx.x * 128;
    int m0 = blockIdx.y * 128;
    int cblk = j0 / chanWidth;
    int jB0 = j0 - cblk * chanWidth;

    const __nv_bfloat16* Ab = A + (size_t)cblk * aChanStride;
    const __nv_bfloat16* Bb = Bx + (size_t)cblk * bChanStride;

    float acc[4][4][4];
#pragma unroll
    for (int i = 0; i < 4; i++)
#pragma unroll
        for (int j = 0; j < 4; j++)
#pragma unroll
            for (int r = 0; r < 4; r++) acc[i][j][r] = 0.f;

    const int C = Kex / 64;

    auto ISSUE = [&](int c) {
        uint32_t st = sb + (c % STAGES) * STAGE_BYTES;
        int e0 = c * 64;
#pragma unroll
        for (int i = 0; i < 4; i++) {
            int id = tid + i * 256;
            int row = id >> 3;
            int kg  = id & 7;
            int e = e0 + kg * 8;
            int src;
            if (DT == 2) src = e;
            else         src = e < K ? e : (e < 2 * K ? e - K : e - 2 * K + loOffA);
            cp16(st + row * ROWB + kg * 16,
                 Ab + (size_t)(m0 + row) * lda + src);
            cp16(st + A_BYTES + row * ROWB + kg * 16,
                 Bb + (size_t)(jB0 + row) * Kex + e);
        }
        CP_COMMIT();
    };

    ISSUE(0);
    if (C > 1) ISSUE(1);

    for (int c = 0; c < C; c++) {
        if (c == C - 1) asm volatile("cp.async.wait_group 0;" ::: "memory");
        else            asm volatile("cp.async.wait_group 1;" ::: "memory");
        __syncthreads();
        if (c + STAGES - 1 < C) ISSUE(c + STAGES - 1);

        uint32_t aBase = sb + (c % STAGES) * STAGE_BYTES;
        uint32_t bBase = aBase + A_BYTES;

#pragma unroll
        for (int ks = 0; ks < 4; ks++) {
            uint32_t af[4][4], bf[2][4];
            int kcol = ks * 16 + (lane >> 4) * 8;
#pragma unroll
            for (int i = 0; i < 4; i++) {
                uint32_t addr = aBase + (uint32_t)((warpM * 64 + i * 16 + (lane & 15)) * ROWB + kcol * 2);
                LDSM_X4(af[i][0], af[i][1], af[i][2], af[i][3], addr);
            }
#pragma unroll
            for (int jj = 0; jj < 2; jj++) {
                uint32_t addr = bBase + (uint32_t)((warpN * 32 + jj * 16 + (lane & 15)) * ROWB + kcol * 2);
                LDSM_X4(bf[jj][0], bf[jj][1], bf[jj][2], bf[jj][3], addr);
            }
#pragma unroll
            for (int i = 0; i < 4; i++)
#pragma unroll
                for (int j = 0; j < 4; j++) {
                    int jj = j >> 1, sel = j & 1;
                    if (DT == 0) mma_bf16(acc[i][j], af[i], bf[jj][sel], bf[jj][sel + 2]);
                    else         mma_fp16(acc[i][j], af[i], bf[jj][sel], bf[jj][sel + 2]);
                }
        }
        __syncthreads();
    }

    // ---------------- epilogue ----------------
    int groupID = lane >> 2;
    int tcol = (lane & 3) * 2;

    float bv0[4], bv1[4], wv0[4], wv1[4];
#pragma unroll
    for (int j = 0; j < 4; j++) {
        int colC = jB0 + warpN * 32 + j * 8 + tcol;
        const float* bp = bias + (size_t)cblk * biasChanStride + colC;
        bv0[j] = __ldg(bp);
        bv1[j] = __ldg(bp + 1);
        if (MODE == 3) {
            wv0[j] = __ldg(W3 + (size_t)cblk * CHID + colC);
            wv1[j] = __ldg(W3 + (size_t)cblk * CHID + colC + 1);
        }
    }

#pragma unroll
    for (int i = 0; i < 4; i++) {
        int row0 = m0 + warpM * 64 + i * 16 + groupID;
        int row1 = row0 + 8;
        if (MODE == 3) {
            float p0 = 0.f, p1 = 0.f;
#pragma unroll
            for (int j = 0; j < 4; j++) {
                float v00 = fmaxf(acc[i][j][0] + bv0[j], 0.f);
                float v01 = fmaxf(acc[i][j][1] + bv1[j], 0.f);
                float v10 = fmaxf(acc[i][j][2] + bv0[j], 0.f);
                float v11 = fmaxf(acc[i][j][3] + bv1[j], 0.f);
                p0 += v00 * wv0[j] + v01 * wv1[j];
                p1 += v10 * wv0[j] + v11 * wv1[j];
            }
            p0 += __shfl_xor_sync(0xffffffffu, p0, 1);
            p0 += __shfl_xor_sync(0xffffffffu, p0, 2);
            p1 += __shfl_xor_sync(0xffffffffu, p1, 1);
            p1 += __shfl_xor_sync(0xffffffffu, p1, 2);
            if ((lane & 3) == 0) {
                if (row0 < M) atomicAdd(outp + (size_t)row0 * CHN + cblk, p0);
                if (row1 < M) atomicAdd(outp + (size_t)row1 * CHN + cblk, p1);
            }
        } else {
#pragma unroll
            for (int j = 0; j < 4; j++) {
                int colC = jB0 + warpN * 32 + j * 8 + tcol;
                float v00 = fmaxf(acc[i][j][0] + bv0[j], 0.f);
                float v01 = fmaxf(acc[i][j][1] + bv1[j], 0.f);
                float v10 = fmaxf(acc[i][j][2] + bv0[j], 0.f);
                float v11 = fmaxf(acc[i][j][3] + bv1[j], 0.f);

                if (MODE == 0) {
                    __nv_bfloat16 h00 = __float2bfloat16(v00), h01 = __float2bfloat16(v01);
                    __nv_bfloat16 h10 = __float2bfloat16(v10), h11 = __float2bfloat16(v11);
                    __nv_bfloat16* p0h = outH + (size_t)row0 * ldH + cblk * outHChanStride + colC;
                    __nv_bfloat16* p1h = outH + (size_t)row1 * ldH + cblk * outHChanStride + colC;
                    *(__nv_bfloat162*)p0h = __nv_bfloat162(h00, h01);
                    *(__nv_bfloat162*)p1h = __nv_bfloat162(h10, h11);
                    __nv_bfloat16 l00 = __float2bfloat16(v00 - __bfloat162float(h00));
                    __nv_bfloat16 l01 = __float2bfloat16(v01 - __bfloat162float(h01));
                    __nv_bfloat16 l10 = __float2bfloat16(v10 - __bfloat162float(h10));
                    __nv_bfloat16 l11 = __float2bfloat16(v11 - __bfloat162float(h11));
                    *(__nv_bfloat162*)(p0h + loDeltaOut) = __nv_bfloat162(l00, l01);
                    *(__nv_bfloat162*)(p1h + loDeltaOut) = __nv_bfloat162(l10, l11);
                } else {
                    __half* p0g = outG + (size_t)row0 * ldG + cblk * outGChanStride + colC;
                    __half* p1g = outG + (size_t)row1 * ldG + cblk * outGChanStride + colC;
                    *(__half2*)p0g = __floats2half2_rn(v00, v01);
                    *(__half2*)p1g = __floats2half2_rn(v10, v11);
                    if (MODE == 1 && outF != nullptr) {
                        int gcol = j0 + warpN * 32 + j * 8 + tcol;
                        *(float2*)(outF + (size_t)row0 * ldF + gcol) = make_float2(v00, v01);
                        *(float2*)(outF + (size_t)row1 * ldF + gcol) = make_float2(v10, v11);
                    }
                }
            }
        }
    }
}

__global__ void out_bias_relu_kernel(float* __restrict__ out, const float* __restrict__ b3, int n) {
    int i = blockIdx.x * blockDim.x + threadIdx.x;
    if (i >= n * CHN) return;
    float v = out[i] + b3[i & (CHN - 1)];
    out[i] = v > 0.f ? v : 0.f;
}

// ---------------- launch ----------------
extern "C" void kernel_launch(void* const* d_in, const int* in_sizes, int n_in,
                              void* d_out, int out_size)
{
    const float* x     = (const float*)d_in[0];
    const int*   edge  = (const int*)  d_in[1];
    const float* convW = (const float*)d_in[2];
    const float* convB = (const float*)d_in[3];
    const float* cW1   = (const float*)d_in[4];
    const float* cB1   = (const float*)d_in[5];
    const float* cW2   = (const float*)d_in[6];
    const float* cB2   = (const float*)d_in[7];
    const float* cW3   = (const float*)d_in[8];
    const float* cB3   = (const float*)d_in[9];
    float* out = (float*)d_out;

    int n = in_sizes[0] / DD;
    int E = in_sizes[1] / 2;

    float *cat;
    __nv_bfloat16 *convWex, *a0, *t0, *t1;
    __half *W1p, *W2p, *catF16, *H1;
    int *cnt;
    cudaGetSymbolAddress((void**)&cat, g_cat);
    cudaGetSymbolAddress((void**)&catF16, g_catF16);
    cudaGetSymbolAddress((void**)&a0, g_a0);
    cudaGetSymbolAddress((void**)&t0, g_t0);
    cudaGetSymbolAddress((void**)&t1, g_t1);
    cudaGetSymbolAddress((void**)&H1, g_H1);
    cudaGetSymbolAddress((void**)&convWex, g_convWex);
    cudaGetSymbolAddress((void**)&W1p, g_W1p);
    cudaGetSymbolAddress((void**)&W2p, g_W2p);
    cudaGetSymbolAddress((void**)&cnt, g_cnt);

    const int DSMEM = STAGES * STAGE_BYTES;
    cudaFuncSetAttribute(mma_gemm<0, 0>, cudaFuncAttributeMaxDynamicSharedMemorySize, DSMEM);
    cudaFuncSetAttribute(mma_gemm<1, 0>, cudaFuncAttributeMaxDynamicSharedMemorySize, DSMEM);
    cudaFuncSetAttribute(mma_gemm<2, 2>, cudaFuncAttributeMaxDynamicSharedMemorySize, DSMEM);
    cudaFuncSetAttribute(mma_gemm<3, 2>, cudaFuncAttributeMaxDynamicSharedMemorySize, DSMEM);

    const int mBlocks = (n + 127) / 128;
    const int BIG = 1 << 30;

    // weight expansion
    { dim3 g((128 * 128 + 255) / 256, 9); expand_w_kernel<<<g, 256>>>(convW, convWex, 128, 128); }
    { dim3 g((512 * 256 + 255) / 256, CHN); expand_w16p_kernel<<<g, 256>>>(cW1, W1p, 512, 256); }
    { dim3 g((256 * 256 + 255) / 256, CHN); expand_w16p_kernel<<<g, 256>>>(cW2, W2p, 256, 256); }

    prep_x_kernel<<<(n * 32 + 255) / 256, 256>>>(x, n);

    // CSR build (once)
    cudaMemsetAsync(cnt, 0, (size_t)(n + 1) * sizeof(int), 0);
    hist_kernel<<<(E + 255) / 256, 256>>>(edge, E);
    int nb = (n + 1023) / 1024;
    scan1_kernel<<<nb, 256>>>(n);
    scan2_kernel<<<1, 32>>>(nb);
    scan3_kernel<<<(n + 255) / 256, 256>>>(n, E);
    fill_kernel<<<(E + 255) / 256, 256>>>(edge, E);

    for (int l = 0; l < LL; l++) {
        {
            long th = (long)n * 32;
            gather_kernel<<<(int)((th + 255) / 256), 256>>>(n, l * DD);
        }

        const float* b0 = convB + (size_t)(l * 3 + 0) * DD;
        const float* b1 = convB + (size_t)(l * 3 + 1) * DD;
        const float* b2 = convB + (size_t)(l * 3 + 2) * DD;
        const __nv_bfloat16* B0 = convWex + (size_t)(l * 3 + 0) * 128 * 384;
        const __nv_bfloat16* B1 = convWex + (size_t)(l * 3 + 1) * 128 * 384;
        const __nv_bfloat16* B2 = convWex + (size_t)(l * 3 + 2) * 128 * 384;

        // fp32 cat write is DEAD for the last layer: gather never reads cols 384..511.
        float* catDst = (l < LL - 1) ? (cat + (l + 1) * DD) : nullptr;

        dim3 grid(1, mBlocks);
        mma_gemm<0, 0><<<grid, 256, DSMEM>>>(a0, 256, 0, 128, 128, 384, B0, 0, BIG, b0, 0,
                                             nullptr, 0, t0, 256, 0, 128,
                                             nullptr, 0, 0, nullptr, nullptr, n);
        mma_gemm<0, 0><<<grid, 256, DSMEM>>>(t0, 256, 0, 128, 128, 384, B1, 0, BIG, b1, 0,
                                             nullptr, 0, t1, 256, 0, 128,
                                             nullptr, 0, 0, nullptr, nullptr, n);
        mma_gemm<1, 0><<<grid, 256, DSMEM>>>(t1, 256, 0, 128, 128, 384, B2, 0, BIG, b2, 0,
                                             catDst, OCW,
                                             nullptr, 0, 0, 0,
                                             catF16 + (l + 1) * DD, OCW, 0,
                                             nullptr, nullptr, n);
    }

    // channel MLP layer 1: plain fp16, K=Kex=512 -> H1 fp16 [N,1024]
    {
        dim3 grid((CHN * CHID) / 128, mBlocks);
        mma_gemm<2, 2><<<grid, 256, DSMEM>>>((const __nv_bfloat16*)catF16, OCW, 0, 0, 512, 512,
                                             (const __nv_bfloat16*)W1p, (long)256 * 512, CHID,
                                             cB1, CHID,
                                             nullptr, 0, nullptr, 0, 0, 0,
                                             H1, 1024, CHID,
                                             nullptr, nullptr, n);
    }

    // channel MLP layer 2 + fused final dot: plain fp16, K=Kex=256
    cudaMemsetAsync(out, 0, (size_t)n * CHN * sizeof(float), 0);
    {
        dim3 grid((CHN * CHID) / 128, mBlocks);
        mma_gemm<3, 2><<<grid, 256, DSMEM>>>((const __nv_bfloat16*)H1, 1024, 256, 0, 256, 256,
                                             (const __nv_bfloat16*)W2p, (long)256 * 256, CHID,
                                             cB2, CHID,
                                             nullptr, 0, nullptr, 0, 0, 0,
                                             nullptr, 0, 0,
                                             cW3, out, n);
    }

    out_bias_relu_kernel<<<(n * CHN + 255) / 256, 256>>>(out, cB3, n);
}

// round 17
// speedup vs baseline: 1.0425x; 1.0097x over previous
#include <cuda_runtime.h>
#include <cuda_bf16.h>
#include <cuda_fp16.h>
#include <cstdint>

// Problem constants
#define NMAX   100000
#define NPAD   100128
#define DD     128
#define LL     3
#define OCW    512
#define CHN    4
#define CHID   256
#define EMAX   2000000

// ---------------- static device scratch ----------------
__device__ float g_cat[(size_t)NPAD * OCW];             // fp32 concat (gather source)
__device__ __half g_catF16[(size_t)NPAD * OCW];         // fp16 concat (MLP1 input)
__device__ __nv_bfloat16 g_a0[(size_t)NPAD * 256];      // conv input [hi128|lo128]
__device__ __nv_bfloat16 g_t0[(size_t)NPAD * 256];
__device__ __nv_bfloat16 g_t1[(size_t)NPAD * 256];
__device__ __half g_H1[(size_t)NPAD * 1024];            // fp16 [N,1024]
__device__ __nv_bfloat16 g_convWex[(size_t)9 * 128 * 384];   // bf16x3 [hi|lo|hi]
__device__ __half g_W1p[(size_t)CHN * 256 * 512];            // fp16 plain [N,K]
__device__ __half g_W2p[(size_t)CHN * 256 * 256];            // fp16 plain [N,K]
// CSR
__device__ int g_cnt   [NPAD + 1];
__device__ int g_rowptr[NPAD + 1];
__device__ int g_wp    [NPAD + 1];
__device__ int g_bsum  [256];
__device__ int g_csr   [EMAX];

// ---------------- helpers ----------------
__device__ __forceinline__ uint32_t smem_u32(const void* p) {
    uint32_t r;
    asm("{ .reg .u64 t; cvta.to.shared.u64 t, %1; cvt.u32.u64 %0, t; }" : "=r"(r) : "l"(p));
    return r;
}
#define LDSM_X4(r0, r1, r2, r3, addr) \
    asm volatile("ldmatrix.sync.aligned.m8n8.x4.shared.b16 {%0,%1,%2,%3}, [%4];" \
        : "=r"(r0), "=r"(r1), "=r"(r2), "=r"(r3) : "r"(addr))

__device__ __forceinline__ void mma_bf16(float* c, const uint32_t* a, uint32_t b0, uint32_t b1) {
    asm volatile(
        "mma.sync.aligned.m16n8k16.row.col.f32.bf16.bf16.f32 "
        "{%0,%1,%2,%3}, {%4,%5,%6,%7}, {%8,%9}, {%0,%1,%2,%3};"
        : "+f"(c[0]), "+f"(c[1]), "+f"(c[2]), "+f"(c[3])
        : "r"(a[0]), "r"(a[1]), "r"(a[2]), "r"(a[3]), "r"(b0), "r"(b1));
}
__device__ __forceinline__ void mma_fp16(float* c, const uint32_t* a, uint32_t b0, uint32_t b1) {
    asm volatile(
        "mma.sync.aligned.m16n8k16.row.col.f32.f16.f16.f32 "
        "{%0,%1,%2,%3}, {%4,%5,%6,%7}, {%8,%9}, {%0,%1,%2,%3};"
        : "+f"(c[0]), "+f"(c[1]), "+f"(c[2]), "+f"(c[3])
        : "r"(a[0]), "r"(a[1]), "r"(a[2]), "r"(a[3]), "r"(b0), "r"(b1));
}
__device__ __forceinline__ void cp16(uint32_t dst, const void* src) {
    asm volatile("cp.async.cg.shared.global [%0], [%1], 16;" :: "r"(dst), "l"(src));
}
#define CP_COMMIT() asm volatile("cp.async.commit_group;" ::: "memory")

// ---------------- weight expansion: bf16x3 [hi|lo|hi] ----------------
__global__ void expand_w_kernel(const float* __restrict__ W, __nv_bfloat16* __restrict__ Bex,
                                int K, int N) {
    int mi = blockIdx.y;
    const float* Wm = W + (size_t)mi * K * N;
    __nv_bfloat16* Bm = Bex + (size_t)mi * N * 3 * K;
    int id = blockIdx.x * blockDim.x + threadIdx.x;
    if (id >= K * N) return;
    int k = id / N, n = id % N;
    float w = Wm[id];
    __nv_bfloat16 hi = __float2bfloat16(w);
    __nv_bfloat16 lo = __float2bfloat16(w - __bfloat162float(hi));
    Bm[(size_t)n * 3 * K + k]         = hi;
    Bm[(size_t)n * 3 * K + K + k]     = lo;
    Bm[(size_t)n * 3 * K + 2 * K + k] = hi;
}

// ---------------- weight expansion: plain fp16 [N,K] ----------------
__global__ void expand_w16p_kernel(const float* __restrict__ W, __half* __restrict__ Bp,
                                   int K, int N) {
    int mi = blockIdx.y;
    const float* Wm = W + (size_t)mi * K * N;
    __half* Bm = Bp + (size_t)mi * N * K;
    int id = blockIdx.x * blockDim.x + threadIdx.x;
    if (id >= K * N) return;
    int k = id / N, n = id % N;
    Bm[(size_t)n * K + k] = __float2half(Wm[id]);
}

__device__ __forceinline__ void store_hilo4(__nv_bfloat16* p, int loDelta, float4 v) {
    __nv_bfloat16 h0 = __float2bfloat16(v.x), h1 = __float2bfloat16(v.y);
    __nv_bfloat16 h2 = __float2bfloat16(v.z), h3 = __float2bfloat16(v.w);
    ((__nv_bfloat162*)p)[0] = __nv_bfloat162(h0, h1);
    ((__nv_bfloat162*)p)[1] = __nv_bfloat162(h2, h3);
    __nv_bfloat16 l0 = __float2bfloat16(v.x - __bfloat162float(h0));
    __nv_bfloat16 l1 = __float2bfloat16(v.y - __bfloat162float(h1));
    __nv_bfloat16 l2 = __float2bfloat16(v.z - __bfloat162float(h2));
    __nv_bfloat16 l3 = __float2bfloat16(v.w - __bfloat162float(h3));
    ((__nv_bfloat162*)(p + loDelta))[0] = __nv_bfloat162(l0, l1);
    ((__nv_bfloat162*)(p + loDelta))[1] = __nv_bfloat162(l2, l3);
}

__global__ void prep_x_kernel(const float* __restrict__ x, int n) {
    int i = blockIdx.x * blockDim.x + threadIdx.x;
    if (i >= n * 32) return;
    int row = i >> 5, c4 = i & 31;
    float4 v = ((const float4*)x)[i];
    ((float4*)g_cat)[(size_t)row * 128 + c4] = v;
    __half* p = g_catF16 + (size_t)row * OCW + c4 * 4;
    ((__half2*)p)[0] = __floats2half2_rn(v.x, v.y);
    ((__half2*)p)[1] = __floats2half2_rn(v.z, v.w);
}

// ---------------- CSR build ----------------
__global__ void hist_kernel(const int* __restrict__ edge, int E) {
    int e = blockIdx.x * blockDim.x + threadIdx.x;
    if (e < E) atomicAdd(&g_cnt[__ldg(edge + E + e)], 1);
}
__global__ void scan1_kernel(int n) {
    __shared__ int warpSums[8];
    int t = threadIdx.x;
    int base = blockIdx.x * 1024 + t * 4;
    int v[4];
#pragma unroll
    for (int j = 0; j < 4; j++) v[j] = (base + j < n) ? g_cnt[base + j] : 0;
    int tsum = v[0] + v[1] + v[2] + v[3];
    int lane = t & 31, w = t >> 5;
    int x = tsum;
#pragma unroll
    for (int o = 1; o < 32; o <<= 1) {
        int y = __shfl_up_sync(0xffffffffu, x, o);
        if (lane >= o) x += y;
    }
    int excl = x - tsum;
    if (lane == 31) warpSums[w] = x;
    __syncthreads();
    if (t == 0) {
        int run = 0;
#pragma unroll
        for (int i = 0; i < 8; i++) { int tm = warpSums[i]; warpSums[i] = run; run += tm; }
        g_bsum[blockIdx.x] = run;
    }
    __syncthreads();
    int off = warpSums[w] + excl;
#pragma unroll
    for (int j = 0; j < 4; j++) {
        if (base + j < n) g_rowptr[base + j] = off;
        off += v[j];
    }
}
__global__ void scan2_kernel(int nb) {
    if (threadIdx.x == 0) {
        int run = 0;
        for (int i = 0; i < nb; i++) { int t = g_bsum[i]; g_bsum[i] = run; run += t; }
    }
}
__global__ void scan3_kernel(int n, int E) {
    int i = blockIdx.x * blockDim.x + threadIdx.x;
    if (i < n) {
        int v = g_rowptr[i] + g_bsum[i >> 10];
        g_rowptr[i] = v;
        g_wp[i] = v;
    }
    if (i == 0) g_rowptr[n] = E;
}
__global__ void fill_kernel(const int* __restrict__ edge, int E) {
    int e = blockIdx.x * blockDim.x + threadIdx.x;
    if (e >= E) return;
    int s = __ldg(edge + e);
    int d = __ldg(edge + E + e);
    int pos = atomicAdd(&g_wp[d], 1);
    g_csr[pos] = s;
}

// ---------------- gather + prep fused (unroll-4, order-preserving, PDL) ----------------
__global__ void gather_kernel(int n, int colOff) {
    int w = (blockIdx.x * blockDim.x + threadIdx.x) >> 5;
    int lane = threadIdx.x & 31;
    // rowptr is ready well before our PDL predecessor (conv3 / fill); read pre-sync.
    int beg = 0, end = 0;
    if (w < n) {
        beg = __ldg(&g_rowptr[w]);
        end = __ldg(&g_rowptr[w + 1]);
    }
    cudaGridDependencySynchronize();   // cat columns from predecessor now visible
    if (w >= n) return;
    const float* base = g_cat + colOff + lane * 4;
    float4 s = *(const float4*)(base + (size_t)w * OCW);
    int i = beg;
    for (; i + 3 < end; i += 4) {
        int s0 = __ldg(&g_csr[i]);
        int s1 = __ldg(&g_csr[i + 1]);
        int s2 = __ldg(&g_csr[i + 2]);
        int s3 = __ldg(&g_csr[i + 3]);
        float4 v0 = *(const float4*)(base + (size_t)s0 * OCW);
        float4 v1 = *(const float4*)(base + (size_t)s1 * OCW);
        float4 v2 = *(const float4*)(base + (size_t)s2 * OCW);
        float4 v3 = *(const float4*)(base + (size_t)s3 * OCW);
        s.x += v0.x; s.y += v0.y; s.z += v0.z; s.w += v0.w;
        s.x += v1.x; s.y += v1.y; s.z += v1.z; s.w += v1.w;
        s.x += v2.x; s.y += v2.y; s.z += v2.z; s.w += v2.w;
        s.x += v3.x; s.y += v3.y; s.z += v3.z; s.w += v3.w;
    }
    for (; i < end; i++) {
        int s0 = __ldg(&g_csr[i]);
        float4 v0 = *(const float4*)(base + (size_t)s0 * OCW);
        s.x += v0.x; s.y += v0.y; s.z += v0.z; s.w += v0.w;
    }
    store_hilo4(g_a0 + (size_t)w * 256 + lane * 4, 128, s);
}

// ---------------- mma.sync GEMM, cp.async 3-stage pipeline, PDL B-prefetch ----------------
// DT=0: bf16x3 expanded (Kex=3K), A [hi|..|lo at loOffA], bf16 mma
// DT=2: plain fp16 (Kex=K), src=e
// MODE 0: relu(acc+bias) -> bf16 hi/lo outH
// MODE 1: relu(acc+bias) -> fp16 outG (+ fp32 outF only if non-null)
// MODE 2: relu(acc+bias) -> fp16 outG (channel layout)
// MODE 3: fused final dot -> atomicAdd(outp)
#define STAGES      3
#define ROWB        144
#define A_BYTES     (128 * ROWB)
#define STAGE_BYTES (2 * A_BYTES)

template<int MODE, int DT>
__global__ void __launch_bounds__(256, 2)
mma_gemm(const __nv_bfloat16* __restrict__ A, int lda, int aChanStride, int loOffA,
         int K, int Kex,
         const __nv_bfloat16* __restrict__ Bx, long bChanStride, int chanWidth,
         const float* __restrict__ bias, int biasChanStride,
         float* __restrict__ outF, int ldF,
         __nv_bfloat16* __restrict__ outH, int ldH, int outHChanStride, int loDeltaOut,
         __half* __restrict__ outG, int ldG, int outGChanStride,
         const float* __restrict__ W3, float* __restrict__ outp, int M)
{
    extern __shared__ char smem[];
    uint32_t sb = smem_u32(smem);

    int tid = threadIdx.x;
    int lane = tid & 31;
    int wid = tid >> 5;
    int warpM = wid & 1;
    int warpN = wid >> 1;

    int j0 = blockIdx.x * 128;
    int m0 = blockIdx.y * 128;
    int cblk = j0 / chanWidth;
    int jB0 = j0 - cblk * chanWidth;

    const __nv_bfloat16* Ab = A + (size_t)cblk * aChanStride;
    const __nv_bfloat16* Bb = Bx + (size_t)cblk * bChanStride;

    float acc[4][4][4];
#pragma unroll
    for (int i = 0; i < 4; i++)
#pragma unroll
        for (int j = 0; j < 4; j++)
#pragma unroll
            for (int r = 0; r < 4; r++) acc[i][j][r] = 0.f;

    const int C = Kex / 64;

    auto ISSUE_B = [&](int c) {
        uint32_t st = sb + (c % STAGES) * STAGE_BYTES;
        int e0 = c * 64;
#pragma unroll
        for (int i = 0; i < 4; i++) {
            int id = tid + i * 256;
            int row = id >> 3;
            int kg  = id & 7;
            cp16(st + A_BYTES + row * ROWB + kg * 16,
                 Bb + (size_t)(jB0 + row) * Kex + e0 + kg * 8);
        }
    };
    auto ISSUE_A = [&](int c) {
        uint32_t st = sb + (c % STAGES) * STAGE_BYTES;
        int e0 = c * 64;
#pragma unroll
        for (int i = 0; i < 4; i++) {
            int id = tid + i * 256;
            int row = id >> 3;
            int kg  = id & 7;
            int e = e0 + kg * 8;
            int src;
            if (DT == 2) src = e;
            else         src = e < K ? e : (e < 2 * K ? e - K : e - 2 * K + loOffA);
            cp16(st + row * ROWB + kg * 16,
                 Ab + (size_t)(m0 + row) * lda + src);
        }
    };
    auto ISSUE = [&](int c) { ISSUE_A(c); ISSUE_B(c); CP_COMMIT(); };

    // PDL prologue: weight (B) loads are independent of the predecessor kernel;
    // issue them before the dependency sync, then the dependent A loads.
    // Groups: g0 = {B0, B1, A0}, g1 = {A1} -> identical wait semantics to
    // the original {A0,B0},{A1,B1} grouping at every wait point.
    ISSUE_B(0);
    if (C > 1) ISSUE_B(1);
    cudaGridDependencySynchronize();
    ISSUE_A(0); CP_COMMIT();
    if (C > 1) { ISSUE_A(1); CP_COMMIT(); }

    for (int c = 0; c < C; c++) {
        if (c == C - 1) asm volatile("cp.async.wait_group 0;" ::: "memory");
        else            asm volatile("cp.async.wait_group 1;" ::: "memory");
        __syncthreads();
        if (c + STAGES - 1 < C) ISSUE(c + STAGES - 1);

        uint32_t aBase = sb + (c % STAGES) * STAGE_BYTES;
        uint32_t bBase = aBase + A_BYTES;

#pragma unroll
        for (int ks = 0; ks < 4; ks++) {
            uint32_t af[4][4], bf[2][4];
            int kcol = ks * 16 + (lane >> 4) * 8;
#pragma unroll
            for (int i = 0; i < 4; i++) {
                uint32_t addr = aBase + (uint32_t)((warpM * 64 + i * 16 + (lane & 15)) * ROWB + kcol * 2);
                LDSM_X4(af[i][0], af[i][1], af[i][2], af[i][3], addr);
            }
#pragma unroll
            for (int jj = 0; jj < 2; jj++) {
                uint32_t addr = bBase + (uint32_t)((warpN * 32 + jj * 16 + (lane & 15)) * ROWB + kcol * 2);
                LDSM_X4(bf[jj][0], bf[jj][1], bf[jj][2], bf[jj][3], addr);
            }
#pragma unroll
            for (int i = 0; i < 4; i++)
#pragma unroll
                for (int j = 0; j < 4; j++) {
                    int jj = j >> 1, sel = j & 1;
                    if (DT == 0) mma_bf16(acc[i][j], af[i], bf[jj][sel], bf[jj][sel + 2]);
                    else         mma_fp16(acc[i][j], af[i], bf[jj][sel], bf[jj][sel + 2]);
                }
        }
        __syncthreads();
    }

    // ---------------- epilogue ----------------
    int groupID = lane >> 2;
    int tcol = (lane & 3) * 2;

    float bv0[4], bv1[4], wv0[4], wv1[4];
#pragma unroll
    for (int j = 0; j < 4; j++) {
        int colC = jB0 + warpN * 32 + j * 8 + tcol;
        const float* bp = bias + (size_t)cblk * biasChanStride + colC;
        bv0[j] = __ldg(bp);
        bv1[j] = __ldg(bp + 1);
        if (MODE == 3) {
            wv0[j] = __ldg(W3 + (size_t)cblk * CHID + colC);
            wv1[j] = __ldg(W3 + (size_t)cblk * CHID + colC + 1);
        }
    }

#pragma unroll
    for (int i = 0; i < 4; i++) {
        int row0 = m0 + warpM * 64 + i * 16 + groupID;
        int row1 = row0 + 8;
        if (MODE == 3) {
            float p0 = 0.f, p1 = 0.f;
#pragma unroll
            for (int j = 0; j < 4; j++) {
                float v00 = fmaxf(acc[i][j][0] + bv0[j], 0.f);
                float v01 = fmaxf(acc[i][j][1] + bv1[j], 0.f);
                float v10 = fmaxf(acc[i][j][2] + bv0[j], 0.f);
                float v11 = fmaxf(acc[i][j][3] + bv1[j], 0.f);
                p0 += v00 * wv0[j] + v01 * wv1[j];
                p1 += v10 * wv0[j] + v11 * wv1[j];
            }
            p0 += __shfl_xor_sync(0xffffffffu, p0, 1);
            p0 += __shfl_xor_sync(0xffffffffu, p0, 2);
            p1 += __shfl_xor_sync(0xffffffffu, p1, 1);
            p1 += __shfl_xor_sync(0xffffffffu, p1, 2);
            if ((lane & 3) == 0) {
                if (row0 < M) atomicAdd(outp + (size_t)row0 * CHN + cblk, p0);
                if (row1 < M) atomicAdd(outp + (size_t)row1 * CHN + cblk, p1);
            }
        } else {
#pragma unroll
            for (int j = 0; j < 4; j++) {
                int colC = jB0 + warpN * 32 + j * 8 + tcol;
                float v00 = fmaxf(acc[i][j][0] + bv0[j], 0.f);
                float v01 = fmaxf(acc[i][j][1] + bv1[j], 0.f);
                float v10 = fmaxf(acc[i][j][2] + bv0[j], 0.f);
                float v11 = fmaxf(acc[i][j][3] + bv1[j], 0.f);

                if (MODE == 0) {
                    __nv_bfloat16 h00 = __float2bfloat16(v00), h01 = __float2bfloat16(v01);
                    __nv_bfloat16 h10 = __float2bfloat16(v10), h11 = __float2bfloat16(v11);
                    __nv_bfloat16* p0h = outH + (size_t)row0 * ldH + cblk * outHChanStride + colC;
                    __nv_bfloat16* p1h = outH + (size_t)row1 * ldH + cblk * outHChanStride + colC;
                    *(__nv_bfloat162*)p0h = __nv_bfloat162(h00, h01);
                    *(__nv_bfloat162*)p1h = __nv_bfloat162(h10, h11);
                    __nv_bfloat16 l00 = __float2bfloat16(v00 - __bfloat162float(h00));
                    __nv_bfloat16 l01 = __float2bfloat16(v01 - __bfloat162float(h01));
                    __nv_bfloat16 l10 = __float2bfloat16(v10 - __bfloat162float(h10));
                    __nv_bfloat16 l11 = __float2bfloat16(v11 - __bfloat162float(h11));
                    *(__nv_bfloat162*)(p0h + loDeltaOut) = __nv_bfloat162(l00, l01);
                    *(__nv_bfloat162*)(p1h + loDeltaOut) = __nv_bfloat162(l10, l11);
                } else {
                    __half* p0g = outG + (size_t)row0 * ldG + cblk * outGChanStride + colC;
                    __half* p1g = outG + (size_t)row1 * ldG + cblk * outGChanStride + colC;
                    *(__half2*)p0g = __floats2half2_rn(v00, v01);
                    *(__half2*)p1g = __floats2half2_rn(v10, v11);
                    if (MODE == 1 && outF != nullptr) {
                        int gcol = j0 + warpN * 32 + j * 8 + tcol;
                        *(float2*)(outF + (size_t)row0 * ldF + gcol) = make_float2(v00, v01);
                        *(float2*)(outF + (size_t)row1 * ldF + gcol) = make_float2(v10, v11);
                    }
                }
            }
        }
    }
}

__global__ void out_bias_relu_kernel(float* __restrict__ out, const float* __restrict__ b3, int n) {
    cudaGridDependencySynchronize();
    int i = blockIdx.x * blockDim.x + threadIdx.x;
    if (i >= n * CHN) return;
    float v = out[i] + b3[i & (CHN - 1)];
    out[i] = v > 0.f ? v : 0.f;
}

// ---------------- PDL launch helper ----------------
template<typename Kern, typename... Args>
static inline void launch_pdl(Kern kern, dim3 grid, dim3 block, size_t smem, Args... args) {
    cudaLaunchConfig_t cfg = {};
    cfg.gridDim = grid;
    cfg.blockDim = block;
    cfg.dynamicSmemBytes = smem;
    cfg.stream = 0;
    cudaLaunchAttribute attr[1];
    attr[0].id = cudaLaunchAttributeProgrammaticStreamSerialization;
    attr[0].val.programmaticStreamSerializationAllowed = 1;
    cfg.attrs = attr;
    cfg.numAttrs = 1;
    cudaLaunchKernelEx(&cfg, kern, args...);
}

// ---------------- launch ----------------
extern "C" void kernel_launch(void* const* d_in, const int* in_sizes, int n_in,
                              void* d_out, int out_size)
{
    const float* x     = (const float*)d_in[0];
    const int*   edge  = (const int*)  d_in[1];
    const float* convW = (const float*)d_in[2];
    const float* convB = (const float*)d_in[3];
    const float* cW1   = (const float*)d_in[4];
    const float* cB1   = (const float*)d_in[5];
    const float* cW2   = (const float*)d_in[6];
    const float* cB2   = (const float*)d_in[7];
    const float* cW3   = (const float*)d_in[8];
    const float* cB3   = (const float*)d_in[9];
    float* out = (float*)d_out;

    int n = in_sizes[0] / DD;
    int E = in_sizes[1] / 2;

    float *cat;
    __nv_bfloat16 *convWex, *a0, *t0, *t1;
    __half *W1p, *W2p, *catF16, *H1;
    int *cnt;
    cudaGetSymbolAddress((void**)&cat, g_cat);
    cudaGetSymbolAddress((void**)&catF16, g_catF16);
    cudaGetSymbolAddress((void**)&a0, g_a0);
    cudaGetSymbolAddress((void**)&t0, g_t0);
    cudaGetSymbolAddress((void**)&t1, g_t1);
    cudaGetSymbolAddress((void**)&H1, g_H1);
    cudaGetSymbolAddress((void**)&convWex, g_convWex);
    cudaGetSymbolAddress((void**)&W1p, g_W1p);
    cudaGetSymbolAddress((void**)&W2p, g_W2p);
    cudaGetSymbolAddress((void**)&cnt, g_cnt);

    const int DSMEM = STAGES * STAGE_BYTES;
    cudaFuncSetAttribute(mma_gemm<0, 0>, cudaFuncAttributeMaxDynamicSharedMemorySize, DSMEM);
    cudaFuncSetAttribute(mma_gemm<1, 0>, cudaFuncAttributeMaxDynamicSharedMemorySize, DSMEM);
    cudaFuncSetAttribute(mma_gemm<2, 2>, cudaFuncAttributeMaxDynamicSharedMemorySize, DSMEM);
    cudaFuncSetAttribute(mma_gemm<3, 2>, cudaFuncAttributeMaxDynamicSharedMemorySize, DSMEM);

    const int mBlocks = (n + 127) / 128;
    const int BIG = 1 << 30;

    // weight expansion
    { dim3 g((128 * 128 + 255) / 256, 9); expand_w_kernel<<<g, 256>>>(convW, convWex, 128, 128); }
    { dim3 g((512 * 256 + 255) / 256, CHN); expand_w16p_kernel<<<g, 256>>>(cW1, W1p, 512, 256); }
    { dim3 g((256 * 256 + 255) / 256, CHN); expand_w16p_kernel<<<g, 256>>>(cW2, W2p, 256, 256); }

    prep_x_kernel<<<(n * 32 + 255) / 256, 256>>>(x, n);

    // out memset early so MLP2's PDL predecessor is a kernel (MLP1), not a memset node
    cudaMemsetAsync(out, 0, (size_t)n * CHN * sizeof(float), 0);

    // CSR build (once)
    cudaMemsetAsync(cnt, 0, (size_t)(n + 1) * sizeof(int), 0);
    hist_kernel<<<(E + 255) / 256, 256>>>(edge, E);
    int nb = (n + 1023) / 1024;
    scan1_kernel<<<nb, 256>>>(n);
    scan2_kernel<<<1, 32>>>(nb);
    scan3_kernel<<<(n + 255) / 256, 256>>>(n, E);
    fill_kernel<<<(E + 255) / 256, 256>>>(edge, E);

    for (int l = 0; l < LL; l++) {
        {
            long th = (long)n * 32;
            launch_pdl(gather_kernel, dim3((unsigned)((th + 255) / 256)), dim3(256), 0,
                       n, l * DD);
        }

        const float* b0 = convB + (size_t)(l * 3 + 0) * DD;
        const float* b1 = convB + (size_t)(l * 3 + 1) * DD;
        const float* b2 = convB + (size_t)(l * 3 + 2) * DD;
        const __nv_bfloat16* B0 = convWex + (size_t)(l * 3 + 0) * 128 * 384;
        const __nv_bfloat16* B1 = convWex + (size_t)(l * 3 + 1) * 128 * 384;
        const __nv_bfloat16* B2 = convWex + (size_t)(l * 3 + 2) * 128 * 384;

        // fp32 cat write is DEAD for the last layer: gather never reads cols 384..511.
        float* catDst = (l < LL - 1) ? (cat + (l + 1) * DD) : nullptr;

        dim3 grid(1, mBlocks);
        launch_pdl(mma_gemm<0, 0>, grid, dim3(256), (size_t)DSMEM,
                   (const __nv_bfloat16*)a0, 256, 0, 128, 128, 384,
                   (const __nv_bfloat16*)B0, (long)0, BIG, b0, 0,
                   (float*)nullptr, 0, (__nv_bfloat16*)t0, 256, 0, 128,
                   (__half*)nullptr, 0, 0, (const float*)nullptr, (float*)nullptr, n);
        launch_pdl(mma_gemm<0, 0>, grid, dim3(256), (size_t)DSMEM,
                   (const __nv_bfloat16*)t0, 256, 0, 128, 128, 384,
                   (const __nv_bfloat16*)B1, (long)0, BIG, b1, 0,
                   (float*)nullptr, 0, (__nv_bfloat16*)t1, 256, 0, 128,
                   (__half*)nullptr, 0, 0, (const float*)nullptr, (float*)nullptr, n);
        launch_pdl(mma_gemm<1, 0>, grid, dim3(256), (size_t)DSMEM,
                   (const __nv_bfloat16*)t1, 256, 0, 128, 128, 384,
                   (const __nv_bfloat16*)B2, (long)0, BIG, b2, 0,
                   catDst, OCW, (__nv_bfloat16*)nullptr, 0, 0, 0,
                   catF16 + (l + 1) * DD, OCW, 0,
                   (const float*)nullptr, (float*)nullptr, n);
    }

    // channel MLP layer 1: plain fp16, K=Kex=512 -> H1 fp16 [N,1024]
    {
        dim3 grid((CHN * CHID) / 128, mBlocks);
        launch_pdl(mma_gemm<2, 2>, grid, dim3(256), (size_t)DSMEM,
                   (const __nv_bfloat16*)catF16, OCW, 0, 0, 512, 512,
                   (const __nv_bfloat16*)W1p, (long)256 * 512, CHID,
                   cB1, CHID,
                   (float*)nullptr, 0, (__nv_bfloat16*)nullptr, 0, 0, 0,
                   H1, 1024, CHID,
                   (const float*)nullptr, (float*)nullptr, n);
    }

    // channel MLP layer 2 + fused final dot: plain fp16, K=Kex=256
    {
        dim3 grid((CHN * CHID) / 128, mBlocks);
        launch_pdl(mma_gemm<3, 2>, grid, dim3(256), (size_t)DSMEM,
                   (const __nv_bfloat16*)H1, 1024, 256, 0, 256, 256,
                   (const __nv_bfloat16*)W2p, (long)256 * 256, CHID,
                   cB2, CHID,
                   (float*)nullptr, 0, (__nv_bfloat16*)nullptr, 0, 0, 0,
                   (__half*)nullptr, 0, 0,
                   cW3, out, n);
    }

    launch_pdl(out_bias_relu_kernel, dim3((n * CHN + 255) / 256), dim3(256), 0,
               out, cB3, n);
}